// round 2
// baseline (speedup 1.0000x reference)
#include <cuda_runtime.h>
#include <math.h>

#define HEADS 8
#define AGENTS 49
#define WIN 32
#define BATCH 32
#define NTOK 1024
#define CH 256
#define HD 32
#define SCALE 0.17677669529663687f  // 32^-0.5

// ---------------- scratch (device globals; no runtime allocation) -----------
__device__ float g_q[BATCH*HEADS*NTOK*HD];    // (b,h,i,d)
__device__ float g_k[BATCH*HEADS*NTOK*HD];
__device__ float g_v[BATCH*HEADS*NTOK*HD];
__device__ float g_ah[BATCH*HEADS*AGENTS*HD]; // agent tokens, head layout
__device__ float g_pb[HEADS*AGENTS*NTOK];     // agent-attn position bias
__device__ float g_ab[HEADS*NTOK*AGENTS];     // q-attn position bias
__device__ float g_S1[BATCH*HEADS*AGENTS*NTOK]; // agent-attn scores/probs
__device__ float g_av[BATCH*HEADS*AGENTS*HD]; // agent_v
__device__ float g_attn[BATCH*NTOK*CH];       // attention out + dwc (b,i,c)

__constant__ int c_starts[7] = {0,4,9,13,18,22,27};
__constant__ int c_ends[7]   = {5,10,14,19,23,28,32};

// ---------------- GEMM 1: qkv = xs @ qkv_w^T, scatter to head layout --------
// M=32768 rows (b*1024+i -> x row b*1025+1+i), N=768, K=256
__global__ __launch_bounds__(256) void gemm_qkv(const float* __restrict__ x,
                                                const float* __restrict__ w) {
    __shared__ float As[8][128];
    __shared__ float Bs[8][128];
    const int tid = threadIdx.x;
    const int bm = blockIdx.y, bn = blockIdx.x;
    const int lRow = tid >> 1;
    const int lCol = (tid & 1) << 2;
    const int m0 = bm * 128 + lRow;
    const int bb = m0 >> 10, ii = m0 & 1023;
    const float* arow = x + (bb * 1025 + 1 + ii) * 256;
    const float* brow = w + (bn * 128 + lRow) * 256;
    const int tr = (tid >> 4) << 3;
    const int tc = (tid & 15) << 3;

    float acc[8][8] = {};

    for (int k0 = 0; k0 < 256; k0 += 8) {
        float4 av = *(const float4*)(arow + k0 + lCol);
        float4 bv = *(const float4*)(brow + k0 + lCol);
        As[lCol + 0][lRow] = av.x; As[lCol + 1][lRow] = av.y;
        As[lCol + 2][lRow] = av.z; As[lCol + 3][lRow] = av.w;
        Bs[lCol + 0][lRow] = bv.x; Bs[lCol + 1][lRow] = bv.y;
        Bs[lCol + 2][lRow] = bv.z; Bs[lCol + 3][lRow] = bv.w;
        __syncthreads();
        #pragma unroll
        for (int k = 0; k < 8; k++) {
            float rM[8], rN[8];
            *(float4*)(rM)     = *(const float4*)&As[k][tr];
            *(float4*)(rM + 4) = *(const float4*)&As[k][tr + 4];
            *(float4*)(rN)     = *(const float4*)&Bs[k][tc];
            *(float4*)(rN + 4) = *(const float4*)&Bs[k][tc + 4];
            #pragma unroll
            for (int m = 0; m < 8; m++)
                #pragma unroll
                for (int n = 0; n < 8; n++)
                    acc[m][n] += rM[m] * rN[n];
        }
        __syncthreads();
    }

    #pragma unroll
    for (int m = 0; m < 8; m++) {
        int gm = bm * 128 + tr + m;
        int b_ = gm >> 10, i_ = gm & 1023;
        #pragma unroll
        for (int n4 = 0; n4 < 8; n4 += 4) {
            int gn = bn * 128 + tc + n4;
            int t = gn >> 8, c_ = gn & 255;
            int h = c_ >> 5, d = c_ & 31;
            float* dst = (t == 0) ? g_q : (t == 1) ? g_k : g_v;
            float4 val = make_float4(acc[m][n4], acc[m][n4+1], acc[m][n4+2], acc[m][n4+3]);
            *(float4*)&dst[((b_ * 8 + h) * 1024 + i_) * 32 + d] = val;
        }
    }
}

// ---------------- adaptive avg pool q -> agents ------------------------------
__global__ void pool_kernel() {
    int idx = blockIdx.x * 256 + threadIdx.x;
    if (idx >= BATCH * AGENTS * CH) return;
    int c = idx & 255;
    int a = (idx >> 8) % 49;
    int b = idx / (49 * 256);
    int ay = a / 7, ax = a % 7;
    int h = c >> 5, d = c & 31;
    const float* base = g_q + (b * 8 + h) * 1024 * 32 + d;
    int ys = c_starts[ay], ye = c_ends[ay];
    int xs = c_starts[ax], xe = c_ends[ax];
    float s = 0.f;
    for (int y = ys; y < ye; y++)
        for (int xx = xs; xx < xe; xx++)
            s += base[(y * 32 + xx) * 32];
    s /= (float)((ye - ys) * (xe - xs));
    g_ah[((b * 8 + h) * 49 + a) * 32 + d] = s;
}

// ---------------- bilinear 7x7 -> 32x32 (jax half-pixel + edge-renorm == clamp)
__device__ __forceinline__ float bilerp7(const float* __restrict__ t, int y, int x) {
    float sy = (y + 0.5f) * 0.21875f - 0.5f;
    float sx = (x + 0.5f) * 0.21875f - 0.5f;
    sy = fminf(fmaxf(sy, 0.f), 6.f);
    sx = fminf(fmaxf(sx, 0.f), 6.f);
    int y0 = (int)sy, x0 = (int)sx;
    int y1 = min(y0 + 1, 6), x1 = min(x0 + 1, 6);
    float fy = sy - (float)y0, fx = sx - (float)x0;
    float v00 = t[y0 * 7 + x0], v01 = t[y0 * 7 + x1];
    float v10 = t[y1 * 7 + x0], v11 = t[y1 * 7 + x1];
    return (1.f - fy) * ((1.f - fx) * v00 + fx * v01)
         + fy * ((1.f - fx) * v10 + fx * v11);
}

__global__ void pb_kernel(const float* __restrict__ an,
                          const float* __restrict__ ahb,
                          const float* __restrict__ awb) {
    int idx = blockIdx.x * 256 + threadIdx.x;
    if (idx >= HEADS * AGENTS * NTOK) return;
    int x = idx & 31, y = (idx >> 5) & 31;
    int a = (idx >> 10) % 49, h = idx / (49 * 1024);
    float v = bilerp7(an + (h * 49 + a) * 49, y, x);
    v += ahb[(h * 49 + a) * 32 + y] + awb[(h * 49 + a) * 32 + x];
    g_pb[idx] = v;
}

__global__ void ab_kernel(const float* __restrict__ na,
                          const float* __restrict__ hab,
                          const float* __restrict__ wab) {
    int idx = blockIdx.x * 256 + threadIdx.x;
    if (idx >= HEADS * NTOK * AGENTS) return;
    int a = idx % 49;
    int i = (idx / 49) & 1023;
    int h = idx / (49 * 1024);
    int y = i >> 5, x = i & 31;
    float v = bilerp7(na + (h * 49 + a) * 49, y, x);
    v += hab[(h * 32 + y) * 49 + a] + wab[(h * 32 + x) * 49 + a];
    g_ab[idx] = v;
}

// ---------------- agent-attn scores: S1[bh,a,i] ------------------------------
__global__ __launch_bounds__(128) void scores1_kernel() {
    __shared__ float ahs[49 * 32];
    int bh = blockIdx.y, itile = blockIdx.x;
    int tid = threadIdx.x;
    for (int j = tid; j < 1568; j += 128) ahs[j] = g_ah[bh * 1568 + j];
    __syncthreads();
    int i = itile * 128 + tid;
    float r[32];
    const float4* kr = (const float4*)(g_k + (bh * 1024 + i) * 32);
    #pragma unroll
    for (int j = 0; j < 8; j++) ((float4*)r)[j] = kr[j];
    int h = bh & 7;
    const float* pbb = g_pb + h * 49 * 1024 + i;
    float* s1 = g_S1 + bh * 49 * 1024 + i;
    for (int a = 0; a < 49; a++) {
        float dot = 0.f;
        #pragma unroll
        for (int d = 0; d < 32; d++) dot += ahs[a * 32 + d] * r[d];
        s1[a * 1024] = dot * SCALE + pbb[a * 1024];
    }
}

// ---------------- softmax over 1024 (in place) --------------------------------
__global__ __launch_bounds__(256) void softmax1_kernel() {
    float* row = g_S1 + (size_t)blockIdx.x * 1024;
    int tid = threadIdx.x;
    float v[4];
    #pragma unroll
    for (int j = 0; j < 4; j++) v[j] = row[tid + j * 256];
    float m = fmaxf(fmaxf(v[0], v[1]), fmaxf(v[2], v[3]));
    __shared__ float red[256];
    red[tid] = m; __syncthreads();
    for (int s = 128; s > 0; s >>= 1) {
        if (tid < s) red[tid] = fmaxf(red[tid], red[tid + s]);
        __syncthreads();
    }
    m = red[0]; __syncthreads();
    float sum = 0.f;
    #pragma unroll
    for (int j = 0; j < 4; j++) { v[j] = expf(v[j] - m); sum += v[j]; }
    red[tid] = sum; __syncthreads();
    for (int s = 128; s > 0; s >>= 1) {
        if (tid < s) red[tid] += red[tid + s];
        __syncthreads();
    }
    float inv = 1.f / red[0];
    #pragma unroll
    for (int j = 0; j < 4; j++) row[tid + j * 256] = v[j] * inv;
}

// ---------------- agent_v = P @ V per (b,h) -----------------------------------
__global__ __launch_bounds__(256) void agentv_kernel() {
    __shared__ float Pt[49 * 128];
    __shared__ float Vt[128 * 32];
    int bh = blockIdx.x, tid = threadIdx.x;
    float acc[7] = {};
    const float* vbase = g_v + (size_t)bh * 1024 * 32;
    const float* pbase = g_S1 + (size_t)bh * 49 * 1024;
    for (int it = 0; it < 8; it++) {
        int i0 = it * 128;
        for (int j = tid; j < 4096; j += 256) Vt[j] = vbase[i0 * 32 + j];
        for (int j = tid; j < 6272; j += 256) {
            int a = j >> 7, ii = j & 127;
            Pt[j] = pbase[a * 1024 + i0 + ii];
        }
        __syncthreads();
        #pragma unroll
        for (int r = 0; r < 7; r++) {
            int o = tid + r * 256;
            if (o < 1568) {
                int a = o >> 5, d = o & 31;
                float s = acc[r];
                #pragma unroll 8
                for (int ii = 0; ii < 128; ii++) s += Pt[a * 128 + ii] * Vt[ii * 32 + d];
                acc[r] = s;
            }
        }
        __syncthreads();
    }
    #pragma unroll
    for (int r = 0; r < 7; r++) {
        int o = tid + r * 256;
        if (o < 1568) g_av[bh * 1568 + o] = acc[r];
    }
}

// ---------------- fused q-attn: scores + softmax(49) + @agent_v --------------
__global__ __launch_bounds__(128) void attn2_kernel() {
    __shared__ float ahs[1568];
    __shared__ float avs[1568];
    __shared__ float ss[128 * 49];
    int bh = blockIdx.y, itile = blockIdx.x, tid = threadIdx.x;
    for (int j = tid; j < 1568; j += 128) {
        ahs[j] = g_ah[bh * 1568 + j];
        avs[j] = g_av[bh * 1568 + j];
    }
    __syncthreads();
    int i = itile * 128 + tid;
    int b_ = bh >> 3, h = bh & 7;
    float q[32];
    const float4* qr = (const float4*)(g_q + (bh * 1024 + i) * 32);
    #pragma unroll
    for (int j = 0; j < 8; j++) ((float4*)q)[j] = qr[j];
    const float* ab = g_ab + (h * 1024 + i) * 49;
    float* s = ss + tid * 49;

    float m = -1e30f;
    for (int a = 0; a < 49; a++) {
        float dot = 0.f;
        #pragma unroll
        for (int d = 0; d < 32; d++) dot += q[d] * ahs[a * 32 + d];
        float val = dot * SCALE + ab[a];
        s[a] = val;
        m = fmaxf(m, val);
    }
    float sum = 0.f;
    for (int a = 0; a < 49; a++) {
        float e = expf(s[a] - m);
        s[a] = e;
        sum += e;
    }
    float inv = 1.f / sum;
    float out[32] = {};
    for (int a = 0; a < 49; a++) {
        float p = s[a] * inv;
        #pragma unroll
        for (int d = 0; d < 32; d++) out[d] += p * avs[a * 32 + d];
    }
    float* dst = g_attn + ((b_ * 1024 + i) * 256) + h * 32;
    #pragma unroll
    for (int j = 0; j < 8; j++) ((float4*)dst)[j] = ((const float4*)out)[j];
}

// ---------------- depthwise 3x3 conv on v + add -------------------------------
__global__ void dwc_kernel(const float* __restrict__ w, const float* __restrict__ bias) {
    int idx = blockIdx.x * 256 + threadIdx.x;  // < 32*1024*256
    int c = idx & 255;
    int i = (idx >> 8) & 1023;
    int b = idx >> 18;
    int y = i >> 5, x = i & 31;
    int h = c >> 5, d = c & 31;
    const float* vb = g_v + (size_t)(b * 8 + h) * 1024 * 32 + d;
    const float* wk = w + c * 9;
    float s = bias[c];
    #pragma unroll
    for (int dy = -1; dy <= 1; dy++) {
        int yy = y + dy;
        if (yy < 0 || yy > 31) continue;
        #pragma unroll
        for (int dx = -1; dx <= 1; dx++) {
            int xx = x + dx;
            if (xx < 0 || xx > 31) continue;
            s += vb[(yy * 32 + xx) * 32] * wk[(dy + 1) * 3 + (dx + 1)];
        }
    }
    g_attn[idx] += s;
}

// ---------------- GEMM 2: final = [cls; attn] @ proj_w^T + proj_b ------------
// M = 32*1025 = 32800, N=256, K=256
__global__ __launch_bounds__(256) void gemm_proj(const float* __restrict__ x,
                                                 const float* __restrict__ w,
                                                 const float* __restrict__ bias,
                                                 float* __restrict__ out) {
    const int M = 32 * 1025;
    __shared__ float As[8][128];
    __shared__ float Bs[8][128];
    const int tid = threadIdx.x;
    const int bm = blockIdx.y, bn = blockIdx.x;
    const int lRow = tid >> 1;
    const int lCol = (tid & 1) << 2;
    const int m0 = bm * 128 + lRow;
    const float* arow;
    if (m0 < M) {
        int b_ = m0 / 1025, tt = m0 % 1025;
        arow = (tt == 0) ? (x + (size_t)b_ * 1025 * 256)
                         : (g_attn + (size_t)(b_ * 1024 + tt - 1) * 256);
    } else {
        arow = x;  // safe dummy
    }
    const float* brow = w + (bn * 128 + lRow) * 256;
    const int tr = (tid >> 4) << 3;
    const int tc = (tid & 15) << 3;

    float acc[8][8] = {};

    for (int k0 = 0; k0 < 256; k0 += 8) {
        float4 av = *(const float4*)(arow + k0 + lCol);
        float4 bv = *(const float4*)(brow + k0 + lCol);
        As[lCol + 0][lRow] = av.x; As[lCol + 1][lRow] = av.y;
        As[lCol + 2][lRow] = av.z; As[lCol + 3][lRow] = av.w;
        Bs[lCol + 0][lRow] = bv.x; Bs[lCol + 1][lRow] = bv.y;
        Bs[lCol + 2][lRow] = bv.z; Bs[lCol + 3][lRow] = bv.w;
        __syncthreads();
        #pragma unroll
        for (int k = 0; k < 8; k++) {
            float rM[8], rN[8];
            *(float4*)(rM)     = *(const float4*)&As[k][tr];
            *(float4*)(rM + 4) = *(const float4*)&As[k][tr + 4];
            *(float4*)(rN)     = *(const float4*)&Bs[k][tc];
            *(float4*)(rN + 4) = *(const float4*)&Bs[k][tc + 4];
            #pragma unroll
            for (int m = 0; m < 8; m++)
                #pragma unroll
                for (int n = 0; n < 8; n++)
                    acc[m][n] += rM[m] * rN[n];
        }
        __syncthreads();
    }

    #pragma unroll
    for (int m = 0; m < 8; m++) {
        int gm = bm * 128 + tr + m;
        if (gm >= M) continue;
        #pragma unroll
        for (int n4 = 0; n4 < 8; n4 += 4) {
            int gn = bn * 128 + tc + n4;
            float4 bb = *(const float4*)(bias + gn);
            float4 val = make_float4(acc[m][n4] + bb.x, acc[m][n4+1] + bb.y,
                                     acc[m][n4+2] + bb.z, acc[m][n4+3] + bb.w);
            *(float4*)&out[(size_t)gm * 256 + gn] = val;
        }
    }
}

// ---------------- launch ------------------------------------------------------
extern "C" void kernel_launch(void* const* d_in, const int* in_sizes, int n_in,
                              void* d_out, int out_size) {
    const float* x      = (const float*)d_in[0];
    const float* qkv_w  = (const float*)d_in[1];
    const float* proj_w = (const float*)d_in[2];
    const float* proj_b = (const float*)d_in[3];
    const float* dwc_w  = (const float*)d_in[4];
    const float* dwc_b  = (const float*)d_in[5];
    const float* an_b   = (const float*)d_in[6];
    const float* ah_b   = (const float*)d_in[7];
    const float* aw_b   = (const float*)d_in[8];
    const float* na_b   = (const float*)d_in[9];
    const float* ha_b   = (const float*)d_in[10];
    const float* wa_b   = (const float*)d_in[11];
    float* out = (float*)d_out;

    gemm_qkv<<<dim3(6, 256), 256>>>(x, qkv_w);
    pool_kernel<<<(BATCH * AGENTS * CH + 255) / 256, 256>>>();
    pb_kernel<<<(HEADS * AGENTS * NTOK + 255) / 256, 256>>>(an_b, ah_b, aw_b);
    ab_kernel<<<(HEADS * NTOK * AGENTS + 255) / 256, 256>>>(na_b, ha_b, wa_b);
    scores1_kernel<<<dim3(8, 256), 128>>>();
    softmax1_kernel<<<BATCH * HEADS * AGENTS, 256>>>();
    agentv_kernel<<<256, 256>>>();
    attn2_kernel<<<dim3(8, 256), 128>>>();
    dwc_kernel<<<(BATCH * NTOK * CH) / 256, 256>>>(dwc_w, dwc_b);
    gemm_proj<<<dim3(2, 257), 256>>>(x, proj_w, proj_b, out);
}

// round 3
// speedup vs baseline: 1.8187x; 1.8187x over previous
#include <cuda_runtime.h>
#include <math.h>
#include <stdint.h>

#define HEADS 8
#define AGENTS 49
#define WIN 32
#define BATCH 32
#define NTOK 1024
#define CH 256
#define HD 32
#define SCALE 0.17677669529663687f  // 32^-0.5

// ---------------- scratch (device globals; no runtime allocation) -----------
__device__ float g_q[BATCH*HEADS*NTOK*HD];    // (b,h,i,d)
__device__ float g_k[BATCH*HEADS*NTOK*HD];
__device__ float g_v[BATCH*HEADS*NTOK*HD];
__device__ float g_ah[BATCH*HEADS*AGENTS*HD]; // agent tokens, head layout
__device__ float g_pb[HEADS*AGENTS*NTOK];     // agent-attn position bias
__device__ float g_ab[HEADS*NTOK*AGENTS];     // q-attn position bias
__device__ float g_S1[BATCH*HEADS*AGENTS*NTOK]; // agent-attn scores/probs
__device__ float g_av[BATCH*HEADS*AGENTS*HD]; // agent_v
__device__ float g_attn[BATCH*NTOK*CH];       // attention out + dwc (b,i,c)

__constant__ int c_starts[7] = {0,4,9,13,18,22,27};
__constant__ int c_ends[7]   = {5,10,14,19,23,28,32};

// ---------------- tf32 helpers ----------------------------------------------
__device__ __forceinline__ uint32_t f2tf32(float f) {
    uint32_t r;
    asm("cvt.rna.tf32.f32 %0, %1;" : "=r"(r) : "f"(f));
    return r;
}

__device__ __forceinline__ void mma_tf32(float* c, const uint32_t* a, const uint32_t* b) {
    asm volatile(
        "mma.sync.aligned.m16n8k8.row.col.f32.tf32.tf32.f32 "
        "{%0,%1,%2,%3},{%4,%5,%6,%7},{%8,%9},{%0,%1,%2,%3};"
        : "+f"(c[0]), "+f"(c[1]), "+f"(c[2]), "+f"(c[3])
        : "r"(a[0]), "r"(a[1]), "r"(a[2]), "r"(a[3]), "r"(b[0]), "r"(b[1]));
}

// ---------------- tensor-core GEMM (tf32), BM=128 BN=128 BK=32, 256 thr ------
// QKV=true : A = xs rows (b*1025+1+i), W = qkv_w (768x256), scatter q/k/v head layout
// QKV=false: A = [cls;attn] rows (M=32800), W = proj_w (256x256), out + bias
template<bool QKV>
__global__ __launch_bounds__(256) void gemm_tc(const float* __restrict__ x,
                                               const float* __restrict__ w,
                                               const float* __restrict__ bias,
                                               float* __restrict__ out) {
    __shared__ uint32_t As[128 * 36];
    __shared__ uint32_t Bs[128 * 36];
    const int tid = threadIdx.x;
    const int bm = blockIdx.y, bn = blockIdx.x;
    const int warp = tid >> 5, lane = tid & 31;
    const int g = lane >> 2, t = lane & 3;
    const int wm = warp >> 2, wn = warp & 3;  // 2 x 4 warps, each 64m x 32n
    const int M = QKV ? (BATCH * NTOK) : (BATCH * 1025);

    // per-thread global load pointers (4 rows of A and B each, 1 float4 per row/chunk)
    const float* aptr[4];
    const float* bptr[4];
    int soff[4];
    #pragma unroll
    for (int i = 0; i < 4; i++) {
        int j = tid + i * 256;            // 0..1023
        int row = j >> 3;                 // 0..127
        int col4 = (j & 7) << 2;          // 0,4,..,28
        soff[i] = row * 36 + col4;
        int gm = bm * 128 + row;
        if (QKV) {
            int b_ = gm >> 10, ii = gm & 1023;
            aptr[i] = x + (size_t)(b_ * 1025 + 1 + ii) * 256 + col4;
        } else {
            if (gm < M) {
                int b_ = gm / 1025, tt = gm % 1025;
                aptr[i] = (tt == 0) ? (x + (size_t)b_ * 1025 * 256 + col4)
                                    : (g_attn + (size_t)(b_ * 1024 + tt - 1) * 256 + col4);
            } else {
                aptr[i] = x + col4;  // dummy valid
            }
        }
        bptr[i] = w + (size_t)(bn * 128 + row) * 256 + col4;
    }

    float acc[4][4][4] = {};

    for (int kc = 0; kc < 256; kc += 32) {
        #pragma unroll
        for (int i = 0; i < 4; i++) {
            float4 av = *(const float4*)(aptr[i] + kc);
            float4 bv = *(const float4*)(bptr[i] + kc);
            uint4 au = make_uint4(f2tf32(av.x), f2tf32(av.y), f2tf32(av.z), f2tf32(av.w));
            uint4 bu = make_uint4(f2tf32(bv.x), f2tf32(bv.y), f2tf32(bv.z), f2tf32(bv.w));
            *(uint4*)&As[soff[i]] = au;
            *(uint4*)&Bs[soff[i]] = bu;
        }
        __syncthreads();
        #pragma unroll
        for (int ks = 0; ks < 4; ks++) {
            const int kb = ks * 8;
            uint32_t af[4][4];
            #pragma unroll
            for (int mt = 0; mt < 4; mt++) {
                int mrow = wm * 64 + mt * 16 + g;
                af[mt][0] = As[mrow * 36 + kb + t];
                af[mt][1] = As[(mrow + 8) * 36 + kb + t];
                af[mt][2] = As[mrow * 36 + kb + t + 4];
                af[mt][3] = As[(mrow + 8) * 36 + kb + t + 4];
            }
            uint32_t bf[4][2];
            #pragma unroll
            for (int nt = 0; nt < 4; nt++) {
                int nrow = wn * 32 + nt * 8 + g;
                bf[nt][0] = Bs[nrow * 36 + kb + t];
                bf[nt][1] = Bs[nrow * 36 + kb + t + 4];
            }
            #pragma unroll
            for (int mt = 0; mt < 4; mt++)
                #pragma unroll
                for (int nt = 0; nt < 4; nt++)
                    mma_tf32(acc[mt][nt], af[mt], bf[nt]);
        }
        __syncthreads();
    }

    // epilogue
    #pragma unroll
    for (int mt = 0; mt < 4; mt++) {
        #pragma unroll
        for (int nt = 0; nt < 4; nt++) {
            int coln = bn * 128 + wn * 32 + nt * 8 + 2 * t;
            #pragma unroll
            for (int half = 0; half < 2; half++) {
                int row = bm * 128 + wm * 64 + mt * 16 + g + half * 8;
                float v0 = acc[mt][nt][half * 2 + 0];
                float v1 = acc[mt][nt][half * 2 + 1];
                if (QKV) {
                    int b_ = row >> 10, i_ = row & 1023;
                    int tsel = coln >> 8, c_ = coln & 255;
                    int h = c_ >> 5, d = c_ & 31;
                    float* dst = (tsel == 0) ? g_q : (tsel == 1) ? g_k : g_v;
                    *(float2*)&dst[((size_t)(b_ * 8 + h) * 1024 + i_) * 32 + d] =
                        make_float2(v0, v1);
                } else {
                    if (row < M) {
                        *(float2*)&out[(size_t)row * 256 + coln] =
                            make_float2(v0 + bias[coln], v1 + bias[coln + 1]);
                    }
                }
            }
        }
    }
}

// ---------------- adaptive avg pool q -> agents ------------------------------
__global__ void pool_kernel() {
    int idx = blockIdx.x * 256 + threadIdx.x;
    if (idx >= BATCH * AGENTS * CH) return;
    int c = idx & 255;
    int a = (idx >> 8) % 49;
    int b = idx / (49 * 256);
    int ay = a / 7, ax = a % 7;
    int h = c >> 5, d = c & 31;
    const float* base = g_q + (size_t)(b * 8 + h) * 1024 * 32 + d;
    int ys = c_starts[ay], ye = c_ends[ay];
    int xs = c_starts[ax], xe = c_ends[ax];
    float s = 0.f;
    for (int y = ys; y < ye; y++)
        for (int xx = xs; xx < xe; xx++)
            s += base[(y * 32 + xx) * 32];
    s /= (float)((ye - ys) * (xe - xs));
    g_ah[((size_t)(b * 8 + h) * 49 + a) * 32 + d] = s;
}

// ---------------- bilinear 7x7 -> 32x32 (jax half-pixel == clamped bilerp) ---
__device__ __forceinline__ float bilerp7(const float* __restrict__ t, int y, int x) {
    float sy = (y + 0.5f) * 0.21875f - 0.5f;
    float sx = (x + 0.5f) * 0.21875f - 0.5f;
    sy = fminf(fmaxf(sy, 0.f), 6.f);
    sx = fminf(fmaxf(sx, 0.f), 6.f);
    int y0 = (int)sy, x0 = (int)sx;
    int y1 = min(y0 + 1, 6), x1 = min(x0 + 1, 6);
    float fy = sy - (float)y0, fx = sx - (float)x0;
    float v00 = t[y0 * 7 + x0], v01 = t[y0 * 7 + x1];
    float v10 = t[y1 * 7 + x0], v11 = t[y1 * 7 + x1];
    return (1.f - fy) * ((1.f - fx) * v00 + fx * v01)
         + fy * ((1.f - fx) * v10 + fx * v11);
}

__global__ void pb_kernel(const float* __restrict__ an,
                          const float* __restrict__ ahb,
                          const float* __restrict__ awb) {
    int idx = blockIdx.x * 256 + threadIdx.x;
    if (idx >= HEADS * AGENTS * NTOK) return;
    int x = idx & 31, y = (idx >> 5) & 31;
    int a = (idx >> 10) % 49, h = idx / (49 * 1024);
    float v = bilerp7(an + (h * 49 + a) * 49, y, x);
    v += ahb[(h * 49 + a) * 32 + y] + awb[(h * 49 + a) * 32 + x];
    g_pb[idx] = v;
}

__global__ void ab_kernel(const float* __restrict__ na,
                          const float* __restrict__ hab,
                          const float* __restrict__ wab) {
    int idx = blockIdx.x * 256 + threadIdx.x;
    if (idx >= HEADS * NTOK * AGENTS) return;
    int a = idx % 49;
    int i = (idx / 49) & 1023;
    int h = idx / (49 * 1024);
    int y = i >> 5, x = i & 31;
    float v = bilerp7(na + (h * 49 + a) * 49, y, x);
    v += hab[(h * 32 + y) * 49 + a] + wab[(h * 32 + x) * 49 + a];
    g_ab[idx] = v;
}

// ---------------- agent-attn scores: S1[bh,a,i] ------------------------------
__global__ __launch_bounds__(128) void scores1_kernel() {
    __shared__ float ahs[49 * 32];
    int bh = blockIdx.y, itile = blockIdx.x;
    int tid = threadIdx.x;
    for (int j = tid; j < 1568; j += 128) ahs[j] = g_ah[(size_t)bh * 1568 + j];
    __syncthreads();
    int i = itile * 128 + tid;
    float r[32];
    const float4* kr = (const float4*)(g_k + ((size_t)bh * 1024 + i) * 32);
    #pragma unroll
    for (int j = 0; j < 8; j++) ((float4*)r)[j] = kr[j];
    int h = bh & 7;
    const float* pbb = g_pb + h * 49 * 1024 + i;
    float* s1 = g_S1 + (size_t)bh * 49 * 1024 + i;
    for (int a = 0; a < 49; a++) {
        float dot = 0.f;
        #pragma unroll
        for (int d = 0; d < 32; d++) dot += ahs[a * 32 + d] * r[d];
        s1[a * 1024] = dot * SCALE + pbb[a * 1024];
    }
}

// ---------------- softmax over 1024 (in place) --------------------------------
__global__ __launch_bounds__(256) void softmax1_kernel() {
    float* row = g_S1 + (size_t)blockIdx.x * 1024;
    int tid = threadIdx.x;
    float v[4];
    #pragma unroll
    for (int j = 0; j < 4; j++) v[j] = row[tid + j * 256];
    float m = fmaxf(fmaxf(v[0], v[1]), fmaxf(v[2], v[3]));
    __shared__ float red[256];
    red[tid] = m; __syncthreads();
    for (int s = 128; s > 0; s >>= 1) {
        if (tid < s) red[tid] = fmaxf(red[tid], red[tid + s]);
        __syncthreads();
    }
    m = red[0]; __syncthreads();
    float sum = 0.f;
    #pragma unroll
    for (int j = 0; j < 4; j++) { v[j] = __expf(v[j] - m); sum += v[j]; }
    red[tid] = sum; __syncthreads();
    for (int s = 128; s > 0; s >>= 1) {
        if (tid < s) red[tid] += red[tid + s];
        __syncthreads();
    }
    float inv = 1.f / red[0];
    #pragma unroll
    for (int j = 0; j < 4; j++) row[tid + j * 256] = v[j] * inv;
}

// ---------------- agent_v = P @ V per (b,h) -----------------------------------
__global__ __launch_bounds__(256) void agentv_kernel() {
    __shared__ float Pt[49 * 128];
    __shared__ float Vt[128 * 32];
    int bh = blockIdx.x, tid = threadIdx.x;
    float acc[7] = {};
    const float* vbase = g_v + (size_t)bh * 1024 * 32;
    const float* pbase = g_S1 + (size_t)bh * 49 * 1024;
    for (int it = 0; it < 8; it++) {
        int i0 = it * 128;
        for (int j = tid; j < 4096; j += 256) Vt[j] = vbase[i0 * 32 + j];
        for (int j = tid; j < 6272; j += 256) {
            int a = j >> 7, ii = j & 127;
            Pt[j] = pbase[a * 1024 + i0 + ii];
        }
        __syncthreads();
        #pragma unroll
        for (int r = 0; r < 7; r++) {
            int o = tid + r * 256;
            if (o < 1568) {
                int a = o >> 5, d = o & 31;
                float s = acc[r];
                #pragma unroll 8
                for (int ii = 0; ii < 128; ii++) s += Pt[a * 128 + ii] * Vt[ii * 32 + d];
                acc[r] = s;
            }
        }
        __syncthreads();
    }
    #pragma unroll
    for (int r = 0; r < 7; r++) {
        int o = tid + r * 256;
        if (o < 1568) g_av[(size_t)bh * 1568 + o] = acc[r];
    }
}

// ---------------- fused q-attn: scores + softmax(49) + @agent_v --------------
// scores kept in registers (a-loop fully unrolled); bias staged via smem coalesced
__global__ __launch_bounds__(128) void attn2_kernel() {
    __shared__ float ahs[1568];
    __shared__ float avs[1568];
    __shared__ float abs_s[128 * 49];
    int bh = blockIdx.y, itile = blockIdx.x, tid = threadIdx.x;
    int h = bh & 7, b_ = bh >> 3;
    int i0 = itile * 128;
    for (int j = tid; j < 1568; j += 128) {
        ahs[j] = g_ah[(size_t)bh * 1568 + j];
        avs[j] = g_av[(size_t)bh * 1568 + j];
    }
    const float* abg = g_ab + ((size_t)h * 1024 + i0) * 49;
    for (int j = tid; j < 6272; j += 128) abs_s[j] = abg[j];
    __syncthreads();

    int i = i0 + tid;
    float q[32];
    const float4* qr = (const float4*)(g_q + ((size_t)bh * 1024 + i) * 32);
    #pragma unroll
    for (int j = 0; j < 8; j++) ((float4*)q)[j] = qr[j];
    const float* ab = abs_s + tid * 49;

    float s[49];
    float m = -1e30f;
    #pragma unroll
    for (int a = 0; a < 49; a++) {
        float dot = 0.f;
        #pragma unroll
        for (int d = 0; d < 32; d++) dot += q[d] * ahs[a * 32 + d];
        s[a] = dot * SCALE + ab[a];
        m = fmaxf(m, s[a]);
    }
    float sum = 0.f;
    #pragma unroll
    for (int a = 0; a < 49; a++) {
        s[a] = __expf(s[a] - m);
        sum += s[a];
    }
    float inv = 1.f / sum;
    float out[32] = {};
    #pragma unroll
    for (int a = 0; a < 49; a++) {
        #pragma unroll
        for (int d = 0; d < 32; d++) out[d] += s[a] * avs[a * 32 + d];
    }
    float* dst = g_attn + ((size_t)(b_ * 1024 + i) * 256) + h * 32;
    #pragma unroll
    for (int j = 0; j < 8; j++) {
        float4 o4 = make_float4(out[j*4] * inv, out[j*4+1] * inv,
                                out[j*4+2] * inv, out[j*4+3] * inv);
        ((float4*)dst)[j] = o4;
    }
}

// ---------------- depthwise 3x3 conv on v + add -------------------------------
__global__ void dwc_kernel(const float* __restrict__ w, const float* __restrict__ bias) {
    int idx = blockIdx.x * 256 + threadIdx.x;  // < 32*1024*256
    int c = idx & 255;
    int i = (idx >> 8) & 1023;
    int b = idx >> 18;
    int y = i >> 5, x = i & 31;
    int h = c >> 5, d = c & 31;
    const float* vb = g_v + (size_t)(b * 8 + h) * 1024 * 32 + d;
    const float* wk = w + c * 9;
    float s = bias[c];
    #pragma unroll
    for (int dy = -1; dy <= 1; dy++) {
        int yy = y + dy;
        if (yy < 0 || yy > 31) continue;
        #pragma unroll
        for (int dx = -1; dx <= 1; dx++) {
            int xx = x + dx;
            if (xx < 0 || xx > 31) continue;
            s += vb[(yy * 32 + xx) * 32] * wk[(dy + 1) * 3 + (dx + 1)];
        }
    }
    g_attn[idx] += s;
}

// ---------------- launch ------------------------------------------------------
extern "C" void kernel_launch(void* const* d_in, const int* in_sizes, int n_in,
                              void* d_out, int out_size) {
    const float* x      = (const float*)d_in[0];
    const float* qkv_w  = (const float*)d_in[1];
    const float* proj_w = (const float*)d_in[2];
    const float* proj_b = (const float*)d_in[3];
    const float* dwc_w  = (const float*)d_in[4];
    const float* dwc_b  = (const float*)d_in[5];
    const float* an_b   = (const float*)d_in[6];
    const float* ah_b   = (const float*)d_in[7];
    const float* aw_b   = (const float*)d_in[8];
    const float* na_b   = (const float*)d_in[9];
    const float* ha_b   = (const float*)d_in[10];
    const float* wa_b   = (const float*)d_in[11];
    float* out = (float*)d_out;

    gemm_tc<true><<<dim3(6, 256), 256>>>(x, qkv_w, nullptr, nullptr);
    pool_kernel<<<(BATCH * AGENTS * CH + 255) / 256, 256>>>();
    pb_kernel<<<(HEADS * AGENTS * NTOK + 255) / 256, 256>>>(an_b, ah_b, aw_b);
    ab_kernel<<<(HEADS * NTOK * AGENTS + 255) / 256, 256>>>(na_b, ha_b, wa_b);
    scores1_kernel<<<dim3(8, 256), 128>>>();
    softmax1_kernel<<<BATCH * HEADS * AGENTS, 256>>>();
    agentv_kernel<<<256, 256>>>();
    attn2_kernel<<<dim3(8, 256), 128>>>();
    dwc_kernel<<<(BATCH * NTOK * CH) / 256, 256>>>(dwc_w, dwc_b);
    gemm_tc<false><<<dim3(2, 257), 256>>>(x, proj_w, proj_b, out);
}